// round 16
// baseline (speedup 1.0000x reference)
#include <cuda_runtime.h>
#include <cuda_fp16.h>
#include <math.h>
#include <stdint.h>

#define BB 2
#define NN 1024
#define DD 512
#define HH 8
#define DHH 64
#define HD 512
#define FFD 2048
#define DEPTH 4

// ---------------- device scratch ----------------
__device__ float  g_x  [BB*NN*DD];              // fp32 residual stream
__device__ __half g_xn [BB*NN*DD];
__device__ __half g_qkv[BB*NN*3*HD];
__device__ __half g_ws [DEPTH * BB*NN*HD];      // all 4 layers, batched upfront
__device__ __half g_AC16 [(size_t)BB*HH*NN*NN];
__device__ __half g_BD16 [(size_t)BB*HH*NN*NN];
__device__ __half g_attn16[(size_t)BB*HH*NN*NN];
__device__ __half g_av [BB*NN*HD];
__device__ __half g_h1 [BB*NN*FFD];
__device__ __half g_rcat [BB*NN * 3*DD];
__device__ __half g_pf16 [HD];
__device__ __half g_wqkvT[DEPTH * 3*HD * DD];
__device__ __half g_wcatT[DEPTH * HD * 3*DD];
__device__ __half g_woutT[DEPTH * DD * HD];
__device__ __half g_wff1T[DEPTH * FFD * DD];
__device__ __half g_wff2T[DEPTH * DD * FFD];

__device__ __forceinline__ uint32_t f22h(float a, float b) {
    __half2 h = __floats2half2_rn(a, b);
    return *reinterpret_cast<uint32_t*>(&h);
}
__device__ __forceinline__ uint32_t hadd2u(uint32_t a, uint32_t b) {
    __half2 r = __hadd2(*(__half2*)&a, *(__half2*)&b);
    return *reinterpret_cast<uint32_t*>(&r);
}
__device__ __forceinline__ void mma16(float* d, const uint32_t* a, const uint32_t* b) {
    asm volatile("mma.sync.aligned.m16n8k16.row.col.f32.f16.f16.f32 "
        "{%0,%1,%2,%3}, {%4,%5,%6,%7}, {%8,%9}, {%0,%1,%2,%3};"
        : "+f"(d[0]), "+f"(d[1]), "+f"(d[2]), "+f"(d[3])
        : "r"(a[0]), "r"(a[1]), "r"(a[2]), "r"(a[3]), "r"(b[0]), "r"(b[1]));
}
#define LDSM4(R0,R1,R2,R3,ADDR) \
    asm volatile("ldmatrix.sync.aligned.m8n8.x4.shared.b16 {%0,%1,%2,%3}, [%4];" \
        : "=r"(R0), "=r"(R1), "=r"(R2), "=r"(R3) : "r"(ADDR))
__device__ __forceinline__ void cpa16(uint32_t dst, const void* src) {
    asm volatile("cp.async.cg.shared.global [%0], [%1], 16;" :: "r"(dst), "l"(src));
}
#define CP_COMMIT() asm volatile("cp.async.commit_group;" ::: "memory")
#define CP_WAIT0()  asm volatile("cp.async.wait_group 0;" ::: "memory")

// ---------------- packing ----------------
__global__ void pack_r_kernel(const float* __restrict__ rt, const float* __restrict__ rc,
                              const float* __restrict__ rp) {
    int idx = blockIdx.x * 256 + threadIdx.x;
    int m = idx / (3 * DD), k = idx % (3 * DD);
    float v;
    if (k < DD)            v = rt[m * DD + k];
    else if (k < 2 * DD)   v = rc[m * DD + k - DD];
    else                   v = rp[m * DD + k - 2 * DD];
    g_rcat[idx] = __float2half(v);
}
__global__ void pack_pf_kernel(const float* __restrict__ pf) {
    int i = blockIdx.x * 256 + threadIdx.x;
    if (i < HD) g_pf16[i] = __float2half(pf[i]);
}

// ---------------- weight transpose ----------------
__global__ void transpose_batch(const float* __restrict__ src, __half* __restrict__ dst,
                                int R, int C, int dstStride, int colBase, size_t dstLayer) {
    __shared__ float t[32][33];
    size_t soff = (size_t)blockIdx.z * R * C;
    size_t doff = (size_t)blockIdx.z * dstLayer;
    int c0 = blockIdx.x * 32, r0 = blockIdx.y * 32;
    int x = threadIdx.x, y = threadIdx.y;
#pragma unroll
    for (int i = 0; i < 32; i += 8)
        t[y + i][x] = src[soff + (size_t)(r0 + y + i) * C + c0 + x];
    __syncthreads();
#pragma unroll
    for (int i = 0; i < 32; i += 8)
        dst[doff + (size_t)(c0 + y + i) * dstStride + colBase + r0 + x] = __float2half(t[x][y + i]);
}

// ---------------- layernorm: fp32 in -> fp16 out ----------------
__global__ void ln_kernel(const float* __restrict__ x, const float* __restrict__ g,
                          const float* __restrict__ bta, __half* __restrict__ y) {
    __shared__ float red[128];
    int row = blockIdx.x;
    int tid = threadIdx.x;
    const float4* xr = (const float4*)(x + (size_t)row * DD);
    float4 v = xr[tid];
    red[tid] = v.x + v.y + v.z + v.w;
    __syncthreads();
    for (int o = 64; o > 0; o >>= 1) { if (tid < o) red[tid] += red[tid + o]; __syncthreads(); }
    float mean = red[0] * (1.0f / DD);
    __syncthreads();
    float dx = v.x - mean, dy = v.y - mean, dz = v.z - mean, dw = v.w - mean;
    red[tid] = dx*dx + dy*dy + dz*dz + dw*dw;
    __syncthreads();
    for (int o = 64; o > 0; o >>= 1) { if (tid < o) red[tid] += red[tid + o]; __syncthreads(); }
    float rstd = rsqrtf(red[0] * (1.0f / DD) + 1e-5f);
    float4 gv = ((const float4*)g)[tid];
    float4 bv = ((const float4*)bta)[tid];
    uint2 o2;
    o2.x = f22h(dx * rstd * gv.x + bv.x, dy * rstd * gv.y + bv.y);
    o2.y = f22h(dz * rstd * gv.z + bv.z, dw * rstd * gv.w + bv.w);
    *(uint2*)(y + (size_t)row * DD + tid * 4) = o2;
}

__device__ __forceinline__ float gelu_exact(float v) {
    return 0.5f * v * (1.0f + erff(v * 0.70710678118654752f));
}

// ---------------- fp16 mma GEMM, ldmatrix + cp.async, BK=64 ----------------
#define A_STRIDE 144
#define A_BYTES (128 * A_STRIDE)          // 18432
#define B_STRIDE 144
#define B_BYTES (64 * B_STRIDE)           // 9216
#define MG_SMEM (2 * (A_BYTES + B_BYTES)) // 55296

template<class CT, bool BIAS, bool RES, bool GELU_>
__global__ void __launch_bounds__(256, 2)
mgemm(const __half* __restrict__ A, const __half* __restrict__ Bt, CT* __restrict__ C,
      int Nc, int K, const float* __restrict__ bias, const float* __restrict__ res,
      size_t bzStride, size_t czStride) {
    extern __shared__ char smc[];
    const uint32_t sbase = (uint32_t)__cvta_generic_to_shared(smc);
    const uint32_t aOff[2] = { 0, A_BYTES };
    const uint32_t bOff[2] = { 2 * A_BYTES, 2 * A_BYTES + B_BYTES };

    const int tid = threadIdx.x;
    const int wid = tid >> 5, lid = tid & 31;
    const int row0 = blockIdx.y * 128;
    const int col0 = blockIdx.x * 64;
    const size_t cz = (size_t)blockIdx.z * czStride;

    const int arow = tid >> 1;
    const uint32_t aDstBase = arow * A_STRIDE + (tid & 1) * 64;
    const int brow = tid >> 2;
    const uint32_t bDstBase = brow * B_STRIDE + (tid & 3) * 32;
    const __half* gA = A  + (size_t)(row0 + arow) * K + (tid & 1) * 32;
    const __half* gB = Bt + (size_t)blockIdx.z * bzStride + (size_t)(col0 + brow) * K + (tid & 3) * 16;

    float acc[2][4][4];
#pragma unroll
    for (int mt = 0; mt < 2; mt++)
#pragma unroll
        for (int nt = 0; nt < 4; nt++)
#pragma unroll
            for (int r = 0; r < 4; r++) acc[mt][nt][r] = 0.f;

    auto stage = [&](int p, int c) {
        uint32_t ad = sbase + aOff[p] + aDstBase;
        const __half* as = gA + (size_t)c * 64;
        cpa16(ad,      as);
        cpa16(ad + 16, as + 8);
        cpa16(ad + 32, as + 16);
        cpa16(ad + 48, as + 24);
        uint32_t bd = sbase + bOff[p] + bDstBase;
        const __half* bs = gB + (size_t)c * 64;
        cpa16(bd,      bs);
        cpa16(bd + 16, bs + 8);
        CP_COMMIT();
    };

    const int nch = K >> 6;
    stage(0, 0);
    CP_WAIT0();
    __syncthreads();

    const int wm = (wid & 3) * 32;
    const int wn = (wid >> 2) * 32;
    const uint32_t aLane = (lid & 15) * A_STRIDE + (lid >> 4) * 16;
    const uint32_t bLane = (wn + lid) * B_STRIDE;

    int p = 0;
    for (int c = 0; c < nch; c++) {
        if (c + 1 < nch) stage(1 - p, c + 1);
        const uint32_t aS = sbase + aOff[p];
        const uint32_t bS = sbase + bOff[p];
#pragma unroll
        for (int s = 0; s < 4; s++) {
            const uint32_t kO = s * 32;
            uint32_t afr[2][4];
#pragma unroll
            for (int mt = 0; mt < 2; mt++)
                LDSM4(afr[mt][0], afr[mt][1], afr[mt][2], afr[mt][3],
                      aS + (wm + mt * 16) * A_STRIDE + aLane + kO);
            uint32_t bb0[4], bb1[4];
            LDSM4(bb0[0], bb0[1], bb0[2], bb0[3], bS + bLane + kO);
            LDSM4(bb1[0], bb1[1], bb1[2], bb1[3], bS + bLane + kO + 16);
#pragma unroll
            for (int mt = 0; mt < 2; mt++)
#pragma unroll
                for (int nt = 0; nt < 4; nt++) {
                    uint32_t bfr[2] = { bb0[nt], bb1[nt] };
                    mma16(acc[mt][nt], afr[mt], bfr);
                }
        }
        CP_WAIT0();
        __syncthreads();
        p ^= 1;
    }

    const int g  = lid >> 2;
    const int tg = lid & 3;
#pragma unroll
    for (int mt = 0; mt < 2; mt++) {
#pragma unroll
        for (int rh = 0; rh < 2; rh++) {
            int row = row0 + wm + mt * 16 + g + rh * 8;
#pragma unroll
            for (int nt = 0; nt < 4; nt++) {
                int col = col0 + wn + nt * 8 + tg * 2;
                size_t idx = cz + (size_t)row * Nc + col;
                float v0 = acc[mt][nt][rh * 2 + 0];
                float v1 = acc[mt][nt][rh * 2 + 1];
                if (BIAS)  { float2 bv = *(const float2*)(bias + col); v0 += bv.x; v1 += bv.y; }
                if (RES)   { float2 rv = *(const float2*)(res + (size_t)row * Nc + col); v0 += rv.x; v1 += rv.y; }
                if (GELU_) { v0 = gelu_exact(v0); v1 = gelu_exact(v1); }
                if constexpr (sizeof(CT) == 2) {
                    *(__half2*)((__half*)C + idx) = __floats2half2_rn(v0, v1);
                } else {
                    *(float2*)((float*)C + idx) = make_float2(v0, v1);
                }
            }
        }
    }
}

// ---------------- scores via fp16 mma + ldmatrix (per b,h; K=64) ----------------
#define SC_STRIDE 144
#define SC_MAT (64 * SC_STRIDE)           // 9216 B
#define SC_SMEM (3 * SC_MAT)              // 27648 B
__global__ void __launch_bounds__(256, 4)
scores_mma(const __half* __restrict__ qkv, const __half* __restrict__ ws,
           __half* __restrict__ AC, __half* __restrict__ BD) {
    extern __shared__ char smc[];
    const uint32_t sbase = (uint32_t)__cvta_generic_to_shared(smc);
    const int bh = blockIdx.z;
    const int b = bh >> 3, h = bh & 7;
    const int i0 = blockIdx.y << 6, j0 = blockIdx.x << 6;
    const int tid = threadIdx.x;

    const int r  = tid >> 2;
    const int d0 = (tid & 3) << 4;
    const uint32_t rowO = r * SC_STRIDE + (tid & 3) * 32;
    const __half* qb = qkv + (size_t)(b * NN + i0 + r) * (3 * HD) + h * DHH + d0;
    const __half* kb = qkv + (size_t)(b * NN + j0 + r) * (3 * HD) + HD + h * DHH + d0;
    const __half* wb = ws  + (size_t)(b * NN + j0 + r) * HD + h * DHH + d0;
    const __half* pf = g_pf16 + h * DHH + d0;
    {
        // K, Ws: raw async copies
        cpa16(sbase + SC_MAT + rowO,          kb);
        cpa16(sbase + SC_MAT + rowO + 16,     kb + 8);
        cpa16(sbase + 2 * SC_MAT + rowO,      wb);
        cpa16(sbase + 2 * SC_MAT + rowO + 16, wb + 8);
        CP_COMMIT();
        // Q: manual (bias add)
        uint4 q0 = *(const uint4*)qb, q1 = *(const uint4*)(qb + 8);
        uint4 p0 = *(const uint4*)pf, p1 = *(const uint4*)(pf + 8);
        q0.x = hadd2u(q0.x, p0.x); q0.y = hadd2u(q0.y, p0.y);
        q0.z = hadd2u(q0.z, p0.z); q0.w = hadd2u(q0.w, p0.w);
        q1.x = hadd2u(q1.x, p1.x); q1.y = hadd2u(q1.y, p1.y);
        q1.z = hadd2u(q1.z, p1.z); q1.w = hadd2u(q1.w, p1.w);
        *(uint4*)(smc + rowO)      = q0;
        *(uint4*)(smc + rowO + 16) = q1;
        CP_WAIT0();
    }
    __syncthreads();

    const int wid = tid >> 5, lid = tid & 31;
    const int grp = wid >> 2;
    const int w2  = wid & 3;
    const int wm  = (w2 & 1) * 32;
    const int wn  = (w2 >> 1) * 32;
    const uint32_t aS = sbase;
    const uint32_t bS = sbase + (grp ? 2 * SC_MAT : SC_MAT);
    const uint32_t aLane = (lid & 15) * SC_STRIDE + (lid >> 4) * 16;
    const uint32_t bLane = (wn + lid) * SC_STRIDE;

    float acc[2][4][4];
#pragma unroll
    for (int mt = 0; mt < 2; mt++)
#pragma unroll
        for (int nt = 0; nt < 4; nt++)
#pragma unroll
            for (int q = 0; q < 4; q++) acc[mt][nt][q] = 0.f;

#pragma unroll
    for (int s = 0; s < 4; s++) {
        const uint32_t kO = s * 32;
        uint32_t afr[2][4];
#pragma unroll
        for (int mt = 0; mt < 2; mt++)
            LDSM4(afr[mt][0], afr[mt][1], afr[mt][2], afr[mt][3],
                  aS + (wm + mt * 16) * SC_STRIDE + aLane + kO);
        uint32_t b0[4], b1[4];
        LDSM4(b0[0], b0[1], b0[2], b0[3], bS + bLane + kO);
        LDSM4(b1[0], b1[1], b1[2], b1[3], bS + bLane + kO + 16);
#pragma unroll
        for (int mt = 0; mt < 2; mt++)
#pragma unroll
            for (int nt = 0; nt < 4; nt++) {
                uint32_t bfr[2] = { b0[nt], b1[nt] };
                mma16(acc[mt][nt], afr[mt], bfr);
            }
    }

    __half* Out = grp ? BD : AC;
    const size_t base = ((size_t)bh << 20);
    const int g = lid >> 2, tg = lid & 3;
#pragma unroll
    for (int mt = 0; mt < 2; mt++) {
#pragma unroll
        for (int rh = 0; rh < 2; rh++) {
            int i = i0 + wm + mt * 16 + g + rh * 8;
#pragma unroll
            for (int nt = 0; nt < 4; nt++) {
                int j = j0 + wn + nt * 8 + tg * 2;
                __half2 h2 = __floats2half2_rn(acc[mt][nt][rh * 2 + 0], acc[mt][nt][rh * 2 + 1]);
                *(__half2*)(Out + base + ((size_t)i << 10) + j) = h2;
            }
        }
    }
}

// ---------------- dots + rel_shift + softmax over heads (fp16 in/out) ----------------
template<bool LAST>
__global__ void softmax16(const __half* __restrict__ AC, const __half* __restrict__ BD,
                          __half* __restrict__ attn, float* __restrict__ out_attn) {
    int gid = blockIdx.x * 256 + threadIdx.x;
    int b = gid >> 19;
    int ijp = gid & ((1 << 19) - 1);
    int ij = ijp << 1;
    int i = ij >> 10, j = ij & 1023;

    int m0 = (i + 1) * NN + j;
    int i2a = m0 / (NN + 1);
    int ka  = m0 - i2a * (NN + 1);
    int i2b, kb;
    if (ka == NN) { i2b = i2a + 1; kb = 0; }
    else          { i2b = i2a;     kb = ka + 1; }

    size_t pb = ((size_t)(b * HH)) << 20;
    size_t sa = ((size_t)i2a << 10) + (ka - 1);
    size_t sb = ((size_t)i2b << 10) + (kb - 1);

    float va[8], vb[8];
#pragma unroll
    for (int h = 0; h < 8; h++) {
        size_t hp = pb + ((size_t)h << 20);
        __half2 ac2 = *(const __half2*)(AC + hp + ij);
        float bda = (ka != 0) ? __half2float(BD[hp + sa]) : 0.f;
        float bdb = (kb != 0) ? __half2float(BD[hp + sb]) : 0.f;
        va[h] = (__low2float(ac2)  + bda * (1.0f / 3.0f)) * 0.125f;
        vb[h] = (__high2float(ac2) + bdb * (1.0f / 3.0f)) * 0.125f;
    }
    float mxa = va[0], mxb = vb[0];
#pragma unroll
    for (int h = 1; h < 8; h++) { mxa = fmaxf(mxa, va[h]); mxb = fmaxf(mxb, vb[h]); }
    float sa_ = 0.f, sb_ = 0.f;
#pragma unroll
    for (int h = 0; h < 8; h++) {
        va[h] = __expf(va[h] - mxa); sa_ += va[h];
        vb[h] = __expf(vb[h] - mxb); sb_ += vb[h];
    }
    float ia = 1.0f / sa_, ib = 1.0f / sb_;
#pragma unroll
    for (int h = 0; h < 8; h++) {
        size_t hp = pb + ((size_t)h << 20);
        float oa = va[h] * ia, ob = vb[h] * ib;
        *(__half2*)(attn + hp + ij) = __floats2half2_rn(oa, ob);
        if (LAST) {
            float2 o2 = make_float2(oa, ob);
            *(float2*)(out_attn + hp + ij) = o2;
        }
    }
}

// ---------------- attn(fp16) @ v(fp16) -> av(fp16): ldmatrix A (cp.async), legacy B ----------------
#define AT_STRIDE 80
#define AT_BYTES (128 * AT_STRIDE)         // 10240
#define VBST 72
#define VB_BYTES (16 * VBST * 4)           // 4608
#define AV_SMEM (2 * AT_BYTES + 2 * VB_BYTES)
__global__ void __launch_bounds__(256, 2)
attnv_mma(const __half* __restrict__ attn, const __half* __restrict__ qkv,
          __half* __restrict__ av) {
    extern __shared__ char smc[];
    const uint32_t sbase = (uint32_t)__cvta_generic_to_shared(smc);
    const uint32_t aOff[2] = { 0, AT_BYTES };
    uint32_t* vB[2] = { (uint32_t*)(smc + 2 * AT_BYTES), (uint32_t*)(smc + 2 * AT_BYTES + VB_BYTES) };

    const int bh = blockIdx.y;
    const int b = bh >> 3, h = bh & 7;
    const int i0 = blockIdx.x << 7;
    const int tid = threadIdx.x;
    const int wid = tid >> 5, lid = tid & 31;

    const int arow = tid >> 1;
    const uint32_t aDstBase = arow * AT_STRIDE + (tid & 1) * 32;
    const int jp   = tid >> 4;
    const int d0   = (tid & 15) * 4;
    const __half* gA = attn + ((size_t)bh << 20) + ((size_t)(i0 + arow) << 10) + (tid & 1) * 16;
    const __half* gV = qkv + 2 * HD + h * DHH + d0;

    float acc[2][4][4];
#pragma unroll
    for (int mt = 0; mt < 2; mt++)
#pragma unroll
        for (int nt = 0; nt < 4; nt++)
#pragma unroll
            for (int q = 0; q < 4; q++) acc[mt][nt][q] = 0.f;

    uint32_t bv2[4];
    auto stageA = [&](int p, int c) {
        uint32_t ad = sbase + aOff[p] + aDstBase;
        const __half* as = gA + (size_t)c * 32;
        cpa16(ad, as); cpa16(ad + 16, as + 8);
        CP_COMMIT();
    };
    auto loadV = [&](int jbase) {
        const __half* v0 = gV + (size_t)(b * NN + jbase + 2 * jp) * (3 * HD);
        const __half* v1 = v0 + 3 * HD;
        uint2 a = *(const uint2*)v0;
        uint2 c = *(const uint2*)v1;
        __half2 a0 = *(__half2*)&a.x, a1 = *(__half2*)&a.y;
        __half2 c0 = *(__half2*)&c.x, c1 = *(__half2*)&c.y;
        __half2 r0 = __halves2half2(__low2half(a0),  __low2half(c0));
        __half2 r1 = __halves2half2(__high2half(a0), __high2half(c0));
        __half2 r2 = __halves2half2(__low2half(a1),  __low2half(c1));
        __half2 r3 = __halves2half2(__high2half(a1), __high2half(c1));
        bv2[0] = *(uint32_t*)&r0; bv2[1] = *(uint32_t*)&r1;
        bv2[2] = *(uint32_t*)&r2; bv2[3] = *(uint32_t*)&r3;
    };

    const int nch = NN >> 5;
    stageA(0, 0);
    loadV(0);
    *(uint4*)&vB[0][jp * VBST + d0] = make_uint4(bv2[0], bv2[1], bv2[2], bv2[3]);
    CP_WAIT0();
    __syncthreads();

    const int wm = (wid & 3) * 32;
    const int wn = (wid >> 2) * 32;
    const int g  = lid >> 2;
    const int tg = lid & 3;
    const uint32_t aLane = (lid & 15) * AT_STRIDE + (lid >> 4) * 16;

    int p = 0;
    for (int c = 0; c < nch; c++) {
        if (c + 1 < nch) {
            stageA(1 - p, c + 1);
            loadV((c + 1) * 32);
        }
        const uint32_t aS = sbase + aOff[p];
        const uint32_t* cB = vB[p];
#pragma unroll
        for (int s = 0; s < 2; s++) {
            const int k0 = s * 8;
            uint32_t afr[2][4];
#pragma unroll
            for (int mt = 0; mt < 2; mt++)
                LDSM4(afr[mt][0], afr[mt][1], afr[mt][2], afr[mt][3],
                      aS + (wm + mt * 16) * AT_STRIDE + aLane + s * 32);
            uint32_t bfr[4][2];
#pragma unroll
            for (int nt = 0; nt < 4; nt++) {
                int cn = wn + nt * 8 + g;
                bfr[nt][0] = cB[(k0 + tg)     * VBST + cn];
                bfr[nt][1] = cB[(k0 + tg + 4) * VBST + cn];
            }
#pragma unroll
            for (int mt = 0; mt < 2; mt++)
#pragma unroll
                for (int nt = 0; nt < 4; nt++)
                    mma16(acc[mt][nt], afr[mt], bfr[nt]);
        }
        if (c + 1 < nch)
            *(uint4*)&vB[1 - p][jp * VBST + d0] = make_uint4(bv2[0], bv2[1], bv2[2], bv2[3]);
        CP_WAIT0();
        __syncthreads();
        p ^= 1;
    }

#pragma unroll
    for (int mt = 0; mt < 2; mt++) {
#pragma unroll
        for (int rh = 0; rh < 2; rh++) {
            int row = i0 + wm + mt * 16 + g + rh * 8;
#pragma unroll
            for (int nt = 0; nt < 4; nt++) {
                int col = wn + nt * 8 + tg * 2;
                __half2 h2 = __floats2half2_rn(acc[mt][nt][rh * 2 + 0], acc[mt][nt][rh * 2 + 1]);
                *(__half2*)(av + (size_t)(b * NN + row) * HD + h * DHH + col) = h2;
            }
        }
    }
}

// ---------------- host orchestration ----------------
extern "C" void kernel_launch(void* const* d_in, const int* in_sizes, int n_in,
                              void* d_out, int out_size) {
    (void)in_sizes; (void)n_in; (void)out_size;
    const float* in_x   = (const float*)d_in[0];
    const float* r_t    = (const float*)d_in[1];
    const float* r_c    = (const float*)d_in[2];
    const float* r_p    = (const float*)d_in[3];
    const float* bias_pf= (const float*)d_in[4];
    const float* ln1_g  = (const float*)d_in[5];
    const float* ln1_b  = (const float*)d_in[6];
    const float* w_qkv  = (const float*)d_in[7];
    const float* w_out  = (const float*)d_in[8];
    const float* b_out  = (const float*)d_in[9];
    const float* w_kt   = (const float*)d_in[10];
    const float* w_kc   = (const float*)d_in[11];
    const float* w_kp   = (const float*)d_in[12];
    const float* ln2_g  = (const float*)d_in[13];
    const float* ln2_b  = (const float*)d_in[14];
    const float* w_ff1  = (const float*)d_in[15];
    const float* b_ff1  = (const float*)d_in[16];
    const float* w_ff2  = (const float*)d_in[17];
    const float* b_ff2  = (const float*)d_in[18];

    float* out_x    = (float*)d_out;
    float* out_attn = out_x + (size_t)BB * NN * DD;

    float *p_x;
    __half *p_xn, *p_qkv, *p_ws, *p_av, *p_h1;
    __half *p_AC, *p_BD, *p_attn, *p_rcat;
    __half *p_wqkvT, *p_wcatT, *p_woutT, *p_wff1T, *p_wff2T;
    cudaGetSymbolAddress((void**)&p_x,   g_x);
    cudaGetSymbolAddress((void**)&p_xn,  g_xn);
    cudaGetSymbolAddress((void**)&p_qkv, g_qkv);
    cudaGetSymbolAddress((void**)&p_ws,  g_ws);
    cudaGetSymbolAddress((void**)&p_AC,  g_AC16);
    cudaGetSymbolAddress((void**)&p_BD,  g_BD16);
    cudaGetSymbolAddress((void**)&p_attn,g_attn16);
    cudaGetSymbolAddress((void**)&p_av,  g_av);
    cudaGetSymbolAddress((void**)&p_h1,  g_h1);
    cudaGetSymbolAddress((void**)&p_rcat, g_rcat);
    cudaGetSymbolAddress((void**)&p_wqkvT, g_wqkvT);
    cudaGetSymbolAddress((void**)&p_wcatT, g_wcatT);
    cudaGetSymbolAddress((void**)&p_woutT, g_woutT);
    cudaGetSymbolAddress((void**)&p_wff1T, g_wff1T);
    cudaGetSymbolAddress((void**)&p_wff2T, g_wff2T);

    cudaFuncSetAttribute((const void*)mgemm<__half,false,false,false>, cudaFuncAttributeMaxDynamicSharedMemorySize, MG_SMEM);
    cudaFuncSetAttribute((const void*)mgemm<float,true,true,false>,    cudaFuncAttributeMaxDynamicSharedMemorySize, MG_SMEM);
    cudaFuncSetAttribute((const void*)mgemm<__half,true,false,true>,   cudaFuncAttributeMaxDynamicSharedMemorySize, MG_SMEM);
    cudaFuncSetAttribute((const void*)scores_mma, cudaFuncAttributeMaxDynamicSharedMemorySize, SC_SMEM);
    cudaFuncSetAttribute((const void*)attnv_mma,  cudaFuncAttributeMaxDynamicSharedMemorySize, AV_SMEM);

    const int M = BB * NN;   // 2048
    dim3 t32(32, 8);

    // one-time packing / transposes (fp32 -> fp16)
    pack_r_kernel<<<(BB * NN * 3 * DD) / 256, 256>>>(r_t, r_c, r_p);
    pack_pf_kernel<<<2, 256>>>(bias_pf);
    transpose_batch<<<dim3(48, 16, DEPTH), t32>>>(w_qkv, p_wqkvT, DD, 3*HD, DD, 0, (size_t)3*HD*DD);
    transpose_batch<<<dim3(16, 16, DEPTH), t32>>>(w_kt, p_wcatT, DD, HD, 3*DD, 0,      (size_t)HD*3*DD);
    transpose_batch<<<dim3(16, 16, DEPTH), t32>>>(w_kc, p_wcatT, DD, HD, 3*DD, DD,     (size_t)HD*3*DD);
    transpose_batch<<<dim3(16, 16, DEPTH), t32>>>(w_kp, p_wcatT, DD, HD, 3*DD, 2*DD,   (size_t)HD*3*DD);
    transpose_batch<<<dim3(16, 16, DEPTH), t32>>>(w_out, p_woutT, HD, DD, HD, 0,       (size_t)DD*HD);
    transpose_batch<<<dim3(64, 16, DEPTH), t32>>>(w_ff1, p_wff1T, DD, FFD, DD, 0,      (size_t)FFD*DD);
    transpose_batch<<<dim3(16, 64, DEPTH), t32>>>(w_ff2, p_wff2T, FFD, DD, FFD, 0,     (size_t)DD*FFD);

    // ws for ALL layers in one batched launch (layer-invariant input)
    mgemm<__half,false,false,false><<<dim3(8, 16, DEPTH), 256, MG_SMEM>>>(
        p_rcat, p_wcatT, p_ws, HD, 3 * DD, nullptr, nullptr,
        (size_t)HD * 3 * DD, (size_t)M * HD);

    for (int l = 0; l < DEPTH; l++) {
        const float* xin = (l == 0) ? in_x : p_x;
        ln_kernel<<<M, 128>>>(xin, ln1_g + l * DD, ln1_b + l * DD, p_xn);
        mgemm<__half,false,false,false><<<dim3(24, 16), 256, MG_SMEM>>>(
            p_xn, p_wqkvT + (size_t)l * 3*HD * DD, p_qkv, 3 * HD, DD, nullptr, nullptr, 0, 0);
        scores_mma<<<dim3(16, 16, BB * HH), 256, SC_SMEM>>>(
            p_qkv, p_ws + (size_t)l * M * HD, p_AC, p_BD);
        if (l == DEPTH - 1)
            softmax16<true><<<(BB * NN * NN / 2) / 256, 256>>>(p_AC, p_BD, p_attn, out_attn);
        else
            softmax16<false><<<(BB * NN * NN / 2) / 256, 256>>>(p_AC, p_BD, p_attn, nullptr);
        attnv_mma<<<dim3(8, BB * HH), 256, AV_SMEM>>>(p_attn, p_qkv, p_av);
        mgemm<float,true,true,false><<<dim3(8, 16), 256, MG_SMEM>>>(
            p_av, p_woutT + (size_t)l * DD * HD, p_x, DD, HD, b_out + l * DD, xin, 0, 0);
        ln_kernel<<<M, 128>>>(p_x, ln2_g + l * DD, ln2_b + l * DD, p_xn);
        mgemm<__half,true,false,true><<<dim3(32, 16), 256, MG_SMEM>>>(
            p_xn, p_wff1T + (size_t)l * FFD * DD, p_h1, FFD, DD, b_ff1 + l * FFD, nullptr, 0, 0);
        float* xdst = (l == DEPTH - 1) ? out_x : p_x;
        mgemm<float,true,true,false><<<dim3(8, 16), 256, MG_SMEM>>>(
            p_h1, p_wff2T + (size_t)l * DD * FFD, xdst, DD, FFD, b_ff2 + l * DD, p_x, 0, 0);
    }
}